// round 1
// baseline (speedup 1.0000x reference)
#include <cuda_runtime.h>
#include <math.h>

#define BSZ   8192
#define DDIM  1024
#define HDIM  1024
#define H2DIM 512
#define MMASK 15

// Scratch (no allocations allowed). d_out doubles as the h1 buffer ([M,B,H] == out shape).
__device__ float g_v[BSZ * DDIM];                 // 33.5 MB
__device__ float g_a[BSZ * DDIM];                 // 33.5 MB
__device__ float g_h2[MMASK * BSZ * H2DIM];       // 251.7 MB

// ---------------------------------------------------------------------------
// Generic tiled SGEMM: C[z] = act( A[z] @ B[z] + bias[z] )
//   A: [M_, K_] row-major (+ z*sA)
//   B: TRANSB=0 -> [K_, N_] row-major; TRANSB=1 -> [N_, K_] row-major (i.e. @ W^T)
//   ACT: 0 = none, 1 = exact GELU, 2 = sigmoid
// Tile: 128x128x8, 256 threads, 8x8 accum per thread.
// Dims must be multiples of (128,128,8) — true for all shapes here.
// ---------------------------------------------------------------------------
template <int TRANSB, int ACT>
__global__ __launch_bounds__(256) void gemm_k(
    const float* __restrict__ A, const float* __restrict__ Bw,
    const float* __restrict__ bias, float* __restrict__ C,
    int M_, int N_, int K_,
    long sA, long sB, long sBias, long sC)
{
    __shared__ float As[8][128];
    __shared__ float Bs[8][128];

    const int z = blockIdx.z;
    const float* Ap    = A    + (long)z * sA;
    const float* Bp    = Bw   + (long)z * sB;
    const float* biasp = bias + (long)z * sBias;
    float*       Cp    = C    + (long)z * sC;

    const int n0 = blockIdx.x * 128;
    const int m0 = blockIdx.y * 128;
    const int tid = threadIdx.x;
    const int tx = tid & 15;   // 0..15 -> n sub-tile
    const int ty = tid >> 4;   // 0..15 -> m sub-tile

    float acc[8][8];
#pragma unroll
    for (int i = 0; i < 8; i++)
#pragma unroll
        for (int j = 0; j < 8; j++) acc[i][j] = 0.f;

    const int aRow = tid >> 1;         // 0..127
    const int aCol = (tid & 1) * 4;    // 0 or 4
    const int bRow = tid >> 5;         // 0..7   (normal B)
    const int bCol = (tid & 31) * 4;   // 0..124
    const int bN   = tid >> 1;         // 0..127 (trans B)
    const int bK   = (tid & 1) * 4;

    for (int k0 = 0; k0 < K_; k0 += 8) {
        float4 av = *(const float4*)(Ap + (long)(m0 + aRow) * K_ + k0 + aCol);
        As[aCol + 0][aRow] = av.x;
        As[aCol + 1][aRow] = av.y;
        As[aCol + 2][aRow] = av.z;
        As[aCol + 3][aRow] = av.w;
        if (TRANSB) {
            float4 bv = *(const float4*)(Bp + (long)(n0 + bN) * K_ + k0 + bK);
            Bs[bK + 0][bN] = bv.x;
            Bs[bK + 1][bN] = bv.y;
            Bs[bK + 2][bN] = bv.z;
            Bs[bK + 3][bN] = bv.w;
        } else {
            float4 bv = *(const float4*)(Bp + (long)(k0 + bRow) * N_ + n0 + bCol);
            *(float4*)(&Bs[bRow][bCol]) = bv;
        }
        __syncthreads();

#pragma unroll
        for (int kk = 0; kk < 8; kk++) {
            float ra[8], rb[8];
#pragma unroll
            for (int i = 0; i < 8; i++) ra[i] = As[kk][ty * 8 + i];
#pragma unroll
            for (int j = 0; j < 8; j++) rb[j] = Bs[kk][tx * 8 + j];
#pragma unroll
            for (int i = 0; i < 8; i++)
#pragma unroll
                for (int j = 0; j < 8; j++) acc[i][j] += ra[i] * rb[j];
        }
        __syncthreads();
    }

#pragma unroll
    for (int i = 0; i < 8; i++) {
        const long row = m0 + ty * 8 + i;
#pragma unroll
        for (int j = 0; j < 8; j++) {
            float v = acc[i][j] + biasp[n0 + tx * 8 + j];
            if (ACT == 1) {
                v = 0.5f * v * (1.0f + erff(v * 0.70710678118654752f));
            } else if (ACT == 2) {
                v = 1.0f / (1.0f + expf(-v));
            }
            acc[i][j] = v;
        }
        *(float4*)(Cp + row * N_ + n0 + tx * 8)     = *(float4*)&acc[i][0];
        *(float4*)(Cp + row * N_ + n0 + tx * 8 + 4) = *(float4*)&acc[i][4];
    }
}

// ---------------------------------------------------------------------------
// Per-row LayerNorm (H=1024) + exact GELU, in place on h[M*B, H].
// One block of 256 threads per row; each thread owns 4 elements.
// ---------------------------------------------------------------------------
__global__ __launch_bounds__(256) void ln_gelu_k(
    float* __restrict__ h, const float* __restrict__ gamma,
    const float* __restrict__ beta)
{
    const long r = blockIdx.x;          // 0 .. M*B-1
    const int  m = (int)(r / BSZ);
    float* row = h + r * HDIM;
    const int tid = threadIdx.x;

    float x[4];
#pragma unroll
    for (int i = 0; i < 4; i++) x[i] = row[tid + i * 256];

    __shared__ float red1[8];
    __shared__ float red2[8];

    float s = x[0] + x[1] + x[2] + x[3];
#pragma unroll
    for (int o = 16; o > 0; o >>= 1) s += __shfl_xor_sync(0xffffffffu, s, o);
    if ((tid & 31) == 0) red1[tid >> 5] = s;
    __syncthreads();
    float tot = 0.f;
#pragma unroll
    for (int i = 0; i < 8; i++) tot += red1[i];
    const float mu = tot * (1.0f / HDIM);

    float vs = 0.f;
#pragma unroll
    for (int i = 0; i < 4; i++) { float d = x[i] - mu; vs += d * d; }
#pragma unroll
    for (int o = 16; o > 0; o >>= 1) vs += __shfl_xor_sync(0xffffffffu, vs, o);
    if ((tid & 31) == 0) red2[tid >> 5] = vs;
    __syncthreads();
    float vtot = 0.f;
#pragma unroll
    for (int i = 0; i < 8; i++) vtot += red2[i];
    const float rstd = rsqrtf(vtot * (1.0f / HDIM) + 1e-5f);

    const float* gm = gamma + (long)m * HDIM;
    const float* bm = beta  + (long)m * HDIM;
#pragma unroll
    for (int i = 0; i < 4; i++) {
        const int c = tid + i * 256;
        float y = (x[i] - mu) * rstd * gm[c] + bm[c];
        y = 0.5f * y * (1.0f + erff(y * 0.70710678118654752f));
        row[c] = y;
    }
}

extern "C" void kernel_launch(void* const* d_in, const int* in_sizes, int n_in,
                              void* d_out, int out_size)
{
    const float* x     = (const float*)d_in[0];
    const float* in_w  = (const float*)d_in[1];   // [3D, D]
    const float* in_b  = (const float*)d_in[2];   // [3D]
    const float* out_w = (const float*)d_in[3];   // [D, D]
    const float* out_b = (const float*)d_in[4];   // [D]
    const float* W1    = (const float*)d_in[5];   // [M, D, H]
    const float* b1    = (const float*)d_in[6];   // [M, H]
    const float* ln_g  = (const float*)d_in[7];   // [M, H]
    const float* ln_b  = (const float*)d_in[8];   // [M, H]
    const float* W2    = (const float*)d_in[9];   // [M, H, H2]
    const float* b2    = (const float*)d_in[10];  // [M, H2]
    const float* W3    = (const float*)d_in[11];  // [M, H2, D]
    const float* b3    = (const float*)d_in[12];  // [M, D]
    float* out = (float*)d_out;                   // [M, B, D]

    float *v, *a, *h2;
    cudaGetSymbolAddress((void**)&v,  g_v);
    cudaGetSymbolAddress((void**)&a,  g_a);
    cudaGetSymbolAddress((void**)&h2, g_h2);

    // seq_len==1 => softmax over length-1 axis == 1 => attn == v.
    // Q and K projections are dead; only the V slice of in_proj is used.
    const float* Wv = in_w + (long)2 * DDIM * DDIM;   // rows [2D, 3D)
    const float* bv = in_b + 2 * DDIM;

    dim3 blk(256);

    // v = x @ Wv^T + bv
    gemm_k<1, 0><<<dim3(DDIM / 128, BSZ / 128, 1), blk>>>(
        x, Wv, bv, v, BSZ, DDIM, DDIM, 0, 0, 0, 0);

    // a = v @ out_proj_w^T + out_proj_b
    gemm_k<1, 0><<<dim3(DDIM / 128, BSZ / 128, 1), blk>>>(
        v, out_w, out_b, a, BSZ, DDIM, DDIM, 0, 0, 0, 0);

    // h1[m] = a @ W1[m] + b1[m]   (written into d_out as scratch, [M,B,H])
    gemm_k<0, 0><<<dim3(HDIM / 128, BSZ / 128, MMASK), blk>>>(
        a, W1, b1, out, BSZ, HDIM, DDIM,
        0, (long)DDIM * HDIM, (long)HDIM, (long)BSZ * HDIM);

    // LayerNorm + GELU in place on d_out
    ln_gelu_k<<<MMASK * BSZ, blk>>>(out, ln_g, ln_b);

    // h2[m] = gelu( h1[m] @ W2[m] + b2[m] )
    gemm_k<0, 1><<<dim3(H2DIM / 128, BSZ / 128, MMASK), blk>>>(
        out, W2, b2, h2, BSZ, H2DIM, HDIM,
        (long)BSZ * HDIM, (long)HDIM * H2DIM, (long)H2DIM, (long)BSZ * H2DIM);

    // out[m] = sigmoid( h2[m] @ W3[m] + b3[m] )
    gemm_k<0, 2><<<dim3(DDIM / 128, BSZ / 128, MMASK), blk>>>(
        h2, W3, b3, out, BSZ, DDIM, H2DIM,
        (long)BSZ * H2DIM, (long)H2DIM * DDIM, (long)DDIM, (long)BSZ * DDIM);
}

// round 3
// speedup vs baseline: 3.5141x; 3.5141x over previous
#include <cuda_runtime.h>
#include <cstdint>
#include <math.h>

#define BSZ   8192
#define DDIM  1024
#define HDIM  1024
#define H2DIM 512
#define MMASK 15

// Scratch (no allocations allowed). d_out doubles as the h1 buffer ([M,B,H] == out shape).
__device__ float g_v[BSZ * DDIM];
__device__ float g_a[BSZ * DDIM];
__device__ float g_h2[MMASK * BSZ * H2DIM];

// ---------------------------------------------------------------------------
// helpers
// ---------------------------------------------------------------------------
__device__ __forceinline__ uint32_t smem_u32(const void* p) {
    uint32_t a;
    asm("{ .reg .u64 t; cvta.to.shared.u64 t, %1; cvt.u32.u64 %0, t; }"
        : "=r"(a) : "l"(p));
    return a;
}

#define CP16(saddr, gptr) \
    asm volatile("cp.async.cg.shared.global [%0], [%1], 16;" \
                 :: "r"(saddr), "l"(gptr) : "memory")
#define CP_COMMIT() asm volatile("cp.async.commit_group;" ::: "memory")
#define CP_WAIT(n)  asm volatile("cp.async.wait_group %0;" :: "n"(n) : "memory")

__device__ __forceinline__ uint32_t to_tf32(float f) {
    uint32_t u;
    asm("cvt.rna.tf32.f32 %0, %1;" : "=r"(u) : "f"(f));
    return u;
}

// D += A(16x8) * B(8x8), tf32 inputs, f32 accum
#define MMA_TF32(d, a, b) \
    asm volatile("mma.sync.aligned.m16n8k8.row.col.f32.tf32.tf32.f32 " \
        "{%0,%1,%2,%3}, {%4,%5,%6,%7}, {%8,%9}, {%0,%1,%2,%3};" \
        : "+f"((d)[0]), "+f"((d)[1]), "+f"((d)[2]), "+f"((d)[3]) \
        : "r"((a)[0]), "r"((a)[1]), "r"((a)[2]), "r"((a)[3]), \
          "r"((b)[0]), "r"((b)[1]))

template <int ACT>
__device__ __forceinline__ float act_f(float v) {
    if (ACT == 1) return 0.5f * v * (1.0f + erff(v * 0.70710678118654752f));
    if (ACT == 2) return 1.0f / (1.0f + expf(-v));
    return v;
}

// ---------------------------------------------------------------------------
// tf32 tensor-core GEMM (legacy mma.sync path; tcgen05 not available on this
// toolchain's PTX target).
//   C[z] = act( A[z] @ op(B[z]) + bias[z] )
//   TRANSB=1: B is [N,K] row-major (y = x @ W^T);  TRANSB=0: B is [K,N] row-major
//   ACT: 0 none, 1 exact GELU, 2 sigmoid
// CTA: 128x128 tile, BK=32, 128 threads = 4 warps (2x2), warp tile 64x64.
// Double-buffered smem via cp.async.
// Requires: M%128==0, N%128==0, K%32==0 (true for all shapes here).
// ---------------------------------------------------------------------------
template <int TRANSB, int ACT>
__global__ void __launch_bounds__(128, 2) gemm_mma(
    const float* __restrict__ A, const float* __restrict__ Bw,
    const float* __restrict__ bias, float* __restrict__ C,
    int N_, int K_, long sA, long sB, long sBias, long sC)
{
    // smem layout (floats):
    //   As[2][128][36]                          (pad 36 -> conflict-free frags, 16B rows)
    //   Bs[2][128][36]  (TRANSB=1)  or  Bs[2][32][136]  (TRANSB=0)
    constexpr int ASTR = 36;
    constexpr int ABUF = 128 * 36;
    constexpr int BSTR = TRANSB ? 36 : 136;
    constexpr int BBUF = TRANSB ? 128 * 36 : 32 * 136;

    extern __shared__ __align__(16) float smem[];
    float* As = smem;
    float* Bs = smem + 2 * ABUF;
    const uint32_t sAs = smem_u32(As);
    const uint32_t sBs = smem_u32(Bs);

    const int tid  = threadIdx.x;
    const int lane = tid & 31;
    const int wid  = tid >> 5;
    const int lr = lane >> 2;       // 0..7
    const int lc = lane & 3;        // 0..3
    const int wm = wid >> 1;        // 0..1
    const int wn = wid & 1;         // 0..1

    const int z  = blockIdx.z;
    const int n0 = blockIdx.x * 128;
    const long m0 = (long)blockIdx.y * 128;
    const float* Ap = A + (long)z * sA + m0 * K_;
    const float* Bp = Bw + (long)z * sB;
    const float* bp = bias + (long)z * sBias + n0;
    float* Cp = C + (long)z * sC + m0 * N_ + n0;

    float acc[4][8][4];
#pragma unroll
    for (int i = 0; i < 4; i++)
#pragma unroll
        for (int j = 0; j < 8; j++)
#pragma unroll
            for (int r = 0; r < 4; r++) acc[i][j][r] = 0.f;

    const int nchunks = K_ >> 5;

    // ---- tile loaders (cp.async) ----
    auto load_tiles = [&](int k0, int buf) {
        // A: 128 rows x 32 cols, 8 float4 per thread
#pragma unroll
        for (int j = 0; j < 8; j++) {
            int idx = tid + j * 128;
            int r = idx >> 3, c = (idx & 7) << 2;
            CP16(sAs + (uint32_t)(buf * ABUF + r * ASTR + c) * 4,
                 Ap + (long)r * K_ + k0 + c);
        }
        if (TRANSB) {
            // B[N,K]: tile rows n0..n0+127, cols k0..k0+31 -> Bs[n][k]
#pragma unroll
            for (int j = 0; j < 8; j++) {
                int idx = tid + j * 128;
                int r = idx >> 3, c = (idx & 7) << 2;
                CP16(sBs + (uint32_t)(buf * BBUF + r * BSTR + c) * 4,
                     Bp + (long)(n0 + r) * K_ + k0 + c);
            }
        } else {
            // B[K,N]: tile rows k0..k0+31, cols n0..n0+127 -> Bs[k][n]
#pragma unroll
            for (int j = 0; j < 8; j++) {
                int idx = tid + j * 128;
                int r = idx >> 5, c = (idx & 31) << 2;
                CP16(sBs + (uint32_t)(buf * BBUF + r * BSTR + c) * 4,
                     Bp + (long)(k0 + r) * N_ + n0 + c);
            }
        }
    };

    load_tiles(0, 0);
    CP_COMMIT();

    for (int ch = 0; ch < nchunks; ch++) {
        if (ch + 1 < nchunks) {
            load_tiles((ch + 1) << 5, (ch + 1) & 1);
            CP_COMMIT();
            CP_WAIT(1);
        } else {
            CP_WAIT(0);
        }
        __syncthreads();

        const float* Asb = As + (ch & 1) * ABUF;
        const float* Bsb = Bs + (ch & 1) * BBUF;

#pragma unroll
        for (int kk = 0; kk < 4; kk++) {
            const int k = kk << 3;
            uint32_t ua[4][4], ub[8][2];
#pragma unroll
            for (int mi = 0; mi < 4; mi++) {
                const int rb = wm * 64 + mi * 16 + lr;
                ua[mi][0] = to_tf32(Asb[rb * ASTR + k + lc]);
                ua[mi][1] = to_tf32(Asb[(rb + 8) * ASTR + k + lc]);
                ua[mi][2] = to_tf32(Asb[rb * ASTR + k + lc + 4]);
                ua[mi][3] = to_tf32(Asb[(rb + 8) * ASTR + k + lc + 4]);
            }
#pragma unroll
            for (int ni = 0; ni < 8; ni++) {
                const int nn = wn * 64 + ni * 8 + lr;
                if (TRANSB) {
                    ub[ni][0] = to_tf32(Bsb[nn * BSTR + k + lc]);
                    ub[ni][1] = to_tf32(Bsb[nn * BSTR + k + lc + 4]);
                } else {
                    ub[ni][0] = to_tf32(Bsb[(k + lc) * BSTR + nn]);
                    ub[ni][1] = to_tf32(Bsb[(k + lc + 4) * BSTR + nn]);
                }
            }
#pragma unroll
            for (int mi = 0; mi < 4; mi++)
#pragma unroll
                for (int ni = 0; ni < 8; ni++)
                    MMA_TF32(acc[mi][ni], ua[mi], ub[ni]);
        }
        __syncthreads();
    }

    // ---- epilogue: bias + activation, register -> gmem ----
#pragma unroll
    for (int mi = 0; mi < 4; mi++) {
        const long r0 = wm * 64 + mi * 16 + lr;
#pragma unroll
        for (int ni = 0; ni < 8; ni++) {
            const int col = wn * 64 + ni * 8 + 2 * lc;
            const float bi0 = bp[col], bi1 = bp[col + 1];
            float2 v0, v1;
            v0.x = act_f<ACT>(acc[mi][ni][0] + bi0);
            v0.y = act_f<ACT>(acc[mi][ni][1] + bi1);
            v1.x = act_f<ACT>(acc[mi][ni][2] + bi0);
            v1.y = act_f<ACT>(acc[mi][ni][3] + bi1);
            *(float2*)(Cp + r0 * N_ + col)       = v0;
            *(float2*)(Cp + (r0 + 8) * N_ + col) = v1;
        }
    }
}

// max dynamic smem needed: TRANSB=1 -> (2*4608 + 2*4608)*4 = 73728 B
static constexpr int SMEM_SZ = 73728;

// ---------------------------------------------------------------------------
// Per-row LayerNorm (H=1024) + exact GELU, in place on h[M*B, H].
// ---------------------------------------------------------------------------
__global__ __launch_bounds__(256) void ln_gelu_k(
    float* __restrict__ h, const float* __restrict__ gamma,
    const float* __restrict__ beta)
{
    const long r = blockIdx.x;
    const int  m = (int)(r / BSZ);
    float* row = h + r * HDIM;
    const int tid = threadIdx.x;

    float x[4];
#pragma unroll
    for (int i = 0; i < 4; i++) x[i] = row[tid + i * 256];

    __shared__ float red1[8];
    __shared__ float red2[8];

    float s = x[0] + x[1] + x[2] + x[3];
#pragma unroll
    for (int o = 16; o > 0; o >>= 1) s += __shfl_xor_sync(0xffffffffu, s, o);
    if ((tid & 31) == 0) red1[tid >> 5] = s;
    __syncthreads();
    float tot = 0.f;
#pragma unroll
    for (int i = 0; i < 8; i++) tot += red1[i];
    const float mu = tot * (1.0f / HDIM);

    float vs = 0.f;
#pragma unroll
    for (int i = 0; i < 4; i++) { float d = x[i] - mu; vs += d * d; }
#pragma unroll
    for (int o = 16; o > 0; o >>= 1) vs += __shfl_xor_sync(0xffffffffu, vs, o);
    if ((tid & 31) == 0) red2[tid >> 5] = vs;
    __syncthreads();
    float vtot = 0.f;
#pragma unroll
    for (int i = 0; i < 8; i++) vtot += red2[i];
    const float rstd = rsqrtf(vtot * (1.0f / HDIM) + 1e-5f);

    const float* gm = gamma + (long)m * HDIM;
    const float* bm = beta  + (long)m * HDIM;
#pragma unroll
    for (int i = 0; i < 4; i++) {
        const int c = tid + i * 256;
        float y = (x[i] - mu) * rstd * gm[c] + bm[c];
        y = 0.5f * y * (1.0f + erff(y * 0.70710678118654752f));
        row[c] = y;
    }
}

extern "C" void kernel_launch(void* const* d_in, const int* in_sizes, int n_in,
                              void* d_out, int out_size)
{
    const float* x     = (const float*)d_in[0];
    const float* in_w  = (const float*)d_in[1];   // [3D, D]
    const float* in_b  = (const float*)d_in[2];   // [3D]
    const float* out_w = (const float*)d_in[3];   // [D, D]
    const float* out_b = (const float*)d_in[4];   // [D]
    const float* W1    = (const float*)d_in[5];   // [M, D, H]
    const float* b1    = (const float*)d_in[6];   // [M, H]
    const float* ln_g  = (const float*)d_in[7];   // [M, H]
    const float* ln_b  = (const float*)d_in[8];   // [M, H]
    const float* W2    = (const float*)d_in[9];   // [M, H, H2]
    const float* b2    = (const float*)d_in[10];  // [M, H2]
    const float* W3    = (const float*)d_in[11];  // [M, H2, D]
    const float* b3    = (const float*)d_in[12];  // [M, D]
    float* out = (float*)d_out;                   // [M, B, D]

    float *v, *a, *h2;
    cudaGetSymbolAddress((void**)&v,  g_v);
    cudaGetSymbolAddress((void**)&a,  g_a);
    cudaGetSymbolAddress((void**)&h2, g_h2);

    cudaFuncSetAttribute(gemm_mma<1, 0>, cudaFuncAttributeMaxDynamicSharedMemorySize, SMEM_SZ);
    cudaFuncSetAttribute(gemm_mma<0, 0>, cudaFuncAttributeMaxDynamicSharedMemorySize, SMEM_SZ);
    cudaFuncSetAttribute(gemm_mma<0, 1>, cudaFuncAttributeMaxDynamicSharedMemorySize, SMEM_SZ);
    cudaFuncSetAttribute(gemm_mma<0, 2>, cudaFuncAttributeMaxDynamicSharedMemorySize, SMEM_SZ);

    // seq_len==1 => softmax over length-1 axis == 1 => attn == v.
    // Q and K projections are dead; only the V slice of in_proj is used.
    const float* Wv = in_w + (long)2 * DDIM * DDIM;
    const float* bv = in_b + 2 * DDIM;

    dim3 blk(128);

    // v = x @ Wv^T + bv
    gemm_mma<1, 0><<<dim3(DDIM / 128, BSZ / 128, 1), blk, SMEM_SZ>>>(
        x, Wv, bv, v, DDIM, DDIM, 0, 0, 0, 0);

    // a = v @ out_proj_w^T + out_proj_b
    gemm_mma<1, 0><<<dim3(DDIM / 128, BSZ / 128, 1), blk, SMEM_SZ>>>(
        v, out_w, out_b, a, DDIM, DDIM, 0, 0, 0, 0);

    // h1[m] = a @ W1[m] + b1[m]  (into d_out as scratch, [M,B,H])
    gemm_mma<0, 0><<<dim3(HDIM / 128, BSZ / 128, MMASK), blk, SMEM_SZ>>>(
        a, W1, b1, out, HDIM, DDIM,
        0, (long)DDIM * HDIM, (long)HDIM, (long)BSZ * HDIM);

    // LayerNorm + GELU in place on d_out
    ln_gelu_k<<<MMASK * BSZ, 256>>>(out, ln_g, ln_b);

    // h2[m] = gelu( h1[m] @ W2[m] + b2[m] )
    gemm_mma<0, 1><<<dim3(H2DIM / 128, BSZ / 128, MMASK), blk, SMEM_SZ>>>(
        out, W2, b2, h2, H2DIM, HDIM,
        (long)BSZ * HDIM, (long)HDIM * H2DIM, (long)H2DIM, (long)BSZ * H2DIM);

    // out[m] = sigmoid( h2[m] @ W3[m] + b3[m] )
    gemm_mma<0, 2><<<dim3(DDIM / 128, BSZ / 128, MMASK), blk, SMEM_SZ>>>(
        h2, W3, b3, out, DDIM, H2DIM,
        (long)BSZ * H2DIM, (long)H2DIM * DDIM, (long)DDIM, (long)BSZ * DDIM);
}

// round 4
// speedup vs baseline: 6.5494x; 1.8637x over previous
#include <cuda_runtime.h>
#include <cuda_bf16.h>
#include <cstdint>
#include <math.h>

#define BSZ   8192
#define DDIM  1024
#define HDIM  1024
#define H2DIM 512
#define MMASK 15

typedef __nv_bfloat16 bf16;

// ---------------------------------------------------------------------------
// Scratch (__device__ globals; no allocations allowed)
// ---------------------------------------------------------------------------
__device__ bf16  g_xb [BSZ * DDIM];
__device__ bf16  g_ab [BSZ * DDIM];
__device__ bf16  g_wvt[DDIM * DDIM];            // Wv^T  [c, j]
__device__ bf16  g_wob[DDIM * DDIM];            // Wo    [n, j]
__device__ bf16  g_wcb[DDIM * DDIM];            // Wc = Wo@Wv  [n, k]
__device__ bf16  g_w1b[MMASK * HDIM * DDIM];    // W1^T per m: [H, D]
__device__ bf16  g_w2b[MMASK * H2DIM * HDIM];   // W2^T per m: [H2, H]
__device__ bf16  g_w3b[MMASK * DDIM * H2DIM];   // W3^T per m: [D, H2]
__device__ bf16  g_h1b[MMASK * BSZ * HDIM];
__device__ bf16  g_h2b[MMASK * BSZ * H2DIM];
__device__ float g_bc [DDIM];
__device__ float g_zeros[DDIM];                 // stays zero (zero-initialized)

// ---------------------------------------------------------------------------
// helpers
// ---------------------------------------------------------------------------
__device__ __forceinline__ uint32_t smem_u32(const void* p) {
    uint32_t a;
    asm("{ .reg .u64 t; cvta.to.shared.u64 t, %1; cvt.u32.u64 %0, t; }"
        : "=r"(a) : "l"(p));
    return a;
}

#define CP16(saddr, gptr) \
    asm volatile("cp.async.cg.shared.global [%0], [%1], 16;" \
                 :: "r"(saddr), "l"(gptr) : "memory")
#define CP_COMMIT() asm volatile("cp.async.commit_group;" ::: "memory")
#define CP_WAIT(n)  asm volatile("cp.async.wait_group %0;" :: "n"(n) : "memory")

#define LDSM4(r0, r1, r2, r3, addr) \
    asm volatile("ldmatrix.sync.aligned.m8n8.x4.shared.b16 {%0,%1,%2,%3}, [%4];" \
                 : "=r"(r0), "=r"(r1), "=r"(r2), "=r"(r3) : "r"(addr))

// D += A(16x16) * B(16x8), bf16 inputs, f32 accum
#define MMA_BF16(d, a, b0, b1) \
    asm volatile("mma.sync.aligned.m16n8k16.row.col.f32.bf16.bf16.f32 " \
        "{%0,%1,%2,%3}, {%4,%5,%6,%7}, {%8,%9}, {%0,%1,%2,%3};" \
        : "+f"((d)[0]), "+f"((d)[1]), "+f"((d)[2]), "+f"((d)[3]) \
        : "r"((a)[0]), "r"((a)[1]), "r"((a)[2]), "r"((a)[3]), "r"(b0), "r"(b1))

template <int ACT>
__device__ __forceinline__ float act_f(float v) {
    if (ACT == 1) return 0.5f * v * (1.0f + erff(v * 0.70710678118654752f));
    if (ACT == 2) return 1.0f / (1.0f + expf(-v));
    return v;
}

// ---------------------------------------------------------------------------
// bf16 tensor-core GEMM:  C[z] = act( A[z] @ B[z]^T + bias[z] )
//   A: [M,K] bf16 row-major.  B: [N,K] bf16 row-major.  bias: f32 [N].
//   OUTBF=1 -> C bf16, else f32.  ACT: 0 none, 1 exact GELU, 2 sigmoid.
// CTA 128x128, BK=64, 128 threads = 4 warps (2x2), warp tile 64x64.
// Double-buffered smem via cp.async; ldmatrix fragment loads.
// Requires M%128==0, N%128==0, K%64==0.
// ---------------------------------------------------------------------------
template <int ACT, int OUTBF>
__global__ void __launch_bounds__(128, 2) gemm_bf16(
    const bf16* __restrict__ A, const bf16* __restrict__ Bw,
    const float* __restrict__ bias, void* __restrict__ Cv,
    int N_, int K_, long sA, long sB, long sBias, long sC)
{
    constexpr int BK   = 64;
    constexpr int STR  = 72;          // halves; 144B row stride (9x16B -> conflict-free)
    constexpr int ABUF = 128 * STR;   // halves per buffer

    extern __shared__ __align__(16) bf16 smem[];
    bf16* As = smem;                  // [2][128][STR]
    bf16* Bs = smem + 2 * ABUF;       // [2][128][STR]
    const uint32_t sAs = smem_u32(As);
    const uint32_t sBs = smem_u32(Bs);

    const int tid  = threadIdx.x;
    const int lane = tid & 31;
    const int wid  = tid >> 5;
    const int lr = lane >> 2, lc = lane & 3;
    const int wm = wid >> 1, wn = wid & 1;

    const int z  = blockIdx.z;
    const int n0 = blockIdx.x * 128;
    const long m0 = (long)blockIdx.y * 128;
    const bf16* Ap = A + (long)z * sA + m0 * K_;
    const bf16* Bp = Bw + (long)z * sB + (long)n0 * K_;
    const float* bp = bias + (long)z * sBias + n0;

    // ldmatrix per-thread base offsets (bytes)
    const uint32_t aOff = (uint32_t)(((wm * 64 + (lane & 15)) * STR + (lane >> 4) * 8) * 2);
    const uint32_t bOff = (uint32_t)(((wn * 64 + ((lane >> 4) * 8 + (lane & 7))) * STR
                                      + ((lane >> 3) & 1) * 8) * 2);

    float acc[4][8][4];
#pragma unroll
    for (int i = 0; i < 4; i++)
#pragma unroll
        for (int j = 0; j < 8; j++)
#pragma unroll
            for (int r = 0; r < 4; r++) acc[i][j][r] = 0.f;

    const int nchunks = K_ >> 6;

    auto load_tiles = [&](int k0, int buf) {
#pragma unroll
        for (int j = 0; j < 8; j++) {
            int idx = tid + j * 128;
            int r = idx >> 3, c = (idx & 7) << 3;           // halves
            CP16(sAs + (uint32_t)((buf * ABUF + r * STR + c) * 2),
                 Ap + (long)r * K_ + k0 + c);
        }
#pragma unroll
        for (int j = 0; j < 8; j++) {
            int idx = tid + j * 128;
            int r = idx >> 3, c = (idx & 7) << 3;
            CP16(sBs + (uint32_t)((buf * ABUF + r * STR + c) * 2),
                 Bp + (long)r * K_ + k0 + c);
        }
    };

    load_tiles(0, 0);
    CP_COMMIT();

    for (int ch = 0; ch < nchunks; ch++) {
        if (ch + 1 < nchunks) {
            load_tiles((ch + 1) << 6, (ch + 1) & 1);
            CP_COMMIT();
            CP_WAIT(1);
        } else {
            CP_WAIT(0);
        }
        __syncthreads();

        const uint32_t aBase = sAs + (uint32_t)((ch & 1) * ABUF * 2) + aOff;
        const uint32_t bBase = sBs + (uint32_t)((ch & 1) * ABUF * 2) + bOff;

#pragma unroll
        for (int ks = 0; ks < 4; ks++) {
            uint32_t ua[4][4], ub[4][4];
#pragma unroll
            for (int mi = 0; mi < 4; mi++)
                LDSM4(ua[mi][0], ua[mi][1], ua[mi][2], ua[mi][3],
                      aBase + (uint32_t)(mi * 16 * STR * 2 + ks * 32));
#pragma unroll
            for (int ni2 = 0; ni2 < 4; ni2++)
                LDSM4(ub[ni2][0], ub[ni2][1], ub[ni2][2], ub[ni2][3],
                      bBase + (uint32_t)(ni2 * 16 * STR * 2 + ks * 32));
#pragma unroll
            for (int mi = 0; mi < 4; mi++)
#pragma unroll
                for (int ni2 = 0; ni2 < 4; ni2++) {
                    MMA_BF16(acc[mi][2 * ni2],     ua[mi], ub[ni2][0], ub[ni2][1]);
                    MMA_BF16(acc[mi][2 * ni2 + 1], ua[mi], ub[ni2][2], ub[ni2][3]);
                }
        }
        __syncthreads();
    }

    // ---- epilogue: bias + activation ----
#pragma unroll
    for (int mi = 0; mi < 4; mi++) {
        const long r0 = m0 + wm * 64 + mi * 16 + lr;
#pragma unroll
        for (int ni = 0; ni < 8; ni++) {
            const int col = wn * 64 + ni * 8 + 2 * lc;
            const float bi0 = bp[col], bi1 = bp[col + 1];
            float v0 = act_f<ACT>(acc[mi][ni][0] + bi0);
            float v1 = act_f<ACT>(acc[mi][ni][1] + bi1);
            float v2 = act_f<ACT>(acc[mi][ni][2] + bi0);
            float v3 = act_f<ACT>(acc[mi][ni][3] + bi1);
            if (OUTBF) {
                bf16* Cp = (bf16*)Cv + (long)z * sC;
                *(__nv_bfloat162*)(Cp + r0 * N_ + n0 + col) =
                    __floats2bfloat162_rn(v0, v1);
                *(__nv_bfloat162*)(Cp + (r0 + 8) * N_ + n0 + col) =
                    __floats2bfloat162_rn(v2, v3);
            } else {
                float* Cp = (float*)Cv + (long)z * sC;
                *(float2*)(Cp + r0 * N_ + n0 + col)       = make_float2(v0, v1);
                *(float2*)(Cp + (r0 + 8) * N_ + n0 + col) = make_float2(v2, v3);
            }
        }
    }
}

static constexpr int SMEM_SZ = 4 * 128 * 72 * 2;   // 73728 B

// ---------------------------------------------------------------------------
// fp32 -> bf16 flat convert (n must be divisible by 4)
// ---------------------------------------------------------------------------
__global__ __launch_bounds__(256) void conv_bf16(
    const float* __restrict__ s, bf16* __restrict__ d, long n4)
{
    long i = (long)blockIdx.x * blockDim.x + threadIdx.x;
    if (i < n4) {
        float4 v = ((const float4*)s)[i];
        ((__nv_bfloat162*)d)[2 * i]     = __floats2bfloat162_rn(v.x, v.y);
        ((__nv_bfloat162*)d)[2 * i + 1] = __floats2bfloat162_rn(v.z, v.w);
    }
}

// ---------------------------------------------------------------------------
// fp32 [R,C] -> bf16 [C,R] transpose-convert (R,C multiples of 32), z-batched
// ---------------------------------------------------------------------------
__global__ __launch_bounds__(256) void transp_bf16(
    const float* __restrict__ src, bf16* __restrict__ dst,
    int R, int C, long sS, long sD)
{
    __shared__ float t[32][33];
    const float* s = src + (long)blockIdx.z * sS;
    bf16* d = dst + (long)blockIdx.z * sD;
    const int c0 = blockIdx.x * 32, r0 = blockIdx.y * 32;
    const int tx = threadIdx.x & 31, ty = threadIdx.x >> 5;   // 32 x 8
#pragma unroll
    for (int k = 0; k < 4; k++)
        t[ty + 8 * k][tx] = s[(long)(r0 + ty + 8 * k) * C + c0 + tx];
    __syncthreads();
#pragma unroll
    for (int k = 0; k < 4; k++)
        d[(long)(c0 + ty + 8 * k) * R + r0 + tx] = __float2bfloat16(t[tx][ty + 8 * k]);
}

// ---------------------------------------------------------------------------
// bc[n] = Wo[n,:] . bv + bo[n]
// ---------------------------------------------------------------------------
__global__ __launch_bounds__(256) void bc_k(
    const float* __restrict__ Wo, const float* __restrict__ bv,
    const float* __restrict__ bo, float* __restrict__ bc)
{
    const int n = blockIdx.x, tid = threadIdx.x;
    float s = 0.f;
    for (int j = tid; j < DDIM; j += 256) s += Wo[(long)n * DDIM + j] * bv[j];
#pragma unroll
    for (int o = 16; o > 0; o >>= 1) s += __shfl_xor_sync(0xffffffffu, s, o);
    __shared__ float r[8];
    if ((tid & 31) == 0) r[tid >> 5] = s;
    __syncthreads();
    if (tid == 0) {
        float tot = 0.f;
#pragma unroll
        for (int i = 0; i < 8; i++) tot += r[i];
        bc[n] = tot + bo[n];
    }
}

// ---------------------------------------------------------------------------
// Per-row LayerNorm (H=1024) + exact GELU: fp32 in, bf16 out.
// ---------------------------------------------------------------------------
__global__ __launch_bounds__(256) void ln_gelu_k(
    const float* __restrict__ h, bf16* __restrict__ o,
    const float* __restrict__ gamma, const float* __restrict__ beta)
{
    const long r = blockIdx.x;
    const int  m = (int)(r / BSZ);
    const float* row = h + r * HDIM;
    bf16* orow = o + r * HDIM;
    const int tid = threadIdx.x;

    float x[4];
#pragma unroll
    for (int i = 0; i < 4; i++) x[i] = row[tid + i * 256];

    __shared__ float red1[8];
    __shared__ float red2[8];

    float s = x[0] + x[1] + x[2] + x[3];
#pragma unroll
    for (int off = 16; off > 0; off >>= 1) s += __shfl_xor_sync(0xffffffffu, s, off);
    if ((tid & 31) == 0) red1[tid >> 5] = s;
    __syncthreads();
    float tot = 0.f;
#pragma unroll
    for (int i = 0; i < 8; i++) tot += red1[i];
    const float mu = tot * (1.0f / HDIM);

    float vs = 0.f;
#pragma unroll
    for (int i = 0; i < 4; i++) { float d = x[i] - mu; vs += d * d; }
#pragma unroll
    for (int off = 16; off > 0; off >>= 1) vs += __shfl_xor_sync(0xffffffffu, vs, off);
    if ((tid & 31) == 0) red2[tid >> 5] = vs;
    __syncthreads();
    float vtot = 0.f;
#pragma unroll
    for (int i = 0; i < 8; i++) vtot += red2[i];
    const float rstd = rsqrtf(vtot * (1.0f / HDIM) + 1e-5f);

    const float* gm = gamma + (long)m * HDIM;
    const float* bm = beta  + (long)m * HDIM;
#pragma unroll
    for (int i = 0; i < 4; i++) {
        const int c = tid + i * 256;
        float y = (x[i] - mu) * rstd * gm[c] + bm[c];
        y = 0.5f * y * (1.0f + erff(y * 0.70710678118654752f));
        orow[c] = __float2bfloat16(y);
    }
}

extern "C" void kernel_launch(void* const* d_in, const int* in_sizes, int n_in,
                              void* d_out, int out_size)
{
    const float* x     = (const float*)d_in[0];
    const float* in_w  = (const float*)d_in[1];   // [3D, D]
    const float* in_b  = (const float*)d_in[2];   // [3D]
    const float* out_w = (const float*)d_in[3];   // [D, D]
    const float* out_b = (const float*)d_in[4];   // [D]
    const float* W1    = (const float*)d_in[5];   // [M, D, H]
    const float* b1    = (const float*)d_in[6];   // [M, H]
    const float* ln_g  = (const float*)d_in[7];   // [M, H]
    const float* ln_b  = (const float*)d_in[8];   // [M, H]
    const float* W2    = (const float*)d_in[9];   // [M, H, H2]
    const float* b2    = (const float*)d_in[10];  // [M, H2]
    const float* W3    = (const float*)d_in[11];  // [M, H2, D]
    const float* b3    = (const float*)d_in[12];  // [M, D]
    float* out = (float*)d_out;                   // [M, B, D]

    bf16 *xb, *ab, *wvt, *wob, *wcb, *w1b, *w2b, *w3b, *h1b, *h2b;
    float *bc, *zeros;
    cudaGetSymbolAddress((void**)&xb,  g_xb);
    cudaGetSymbolAddress((void**)&ab,  g_ab);
    cudaGetSymbolAddress((void**)&wvt, g_wvt);
    cudaGetSymbolAddress((void**)&wob, g_wob);
    cudaGetSymbolAddress((void**)&wcb, g_wcb);
    cudaGetSymbolAddress((void**)&w1b, g_w1b);
    cudaGetSymbolAddress((void**)&w2b, g_w2b);
    cudaGetSymbolAddress((void**)&w3b, g_w3b);
    cudaGetSymbolAddress((void**)&h1b, g_h1b);
    cudaGetSymbolAddress((void**)&h2b, g_h2b);
    cudaGetSymbolAddress((void**)&bc,  g_bc);
    cudaGetSymbolAddress((void**)&zeros, g_zeros);

    cudaFuncSetAttribute(gemm_bf16<0, 1>, cudaFuncAttributeMaxDynamicSharedMemorySize, SMEM_SZ);
    cudaFuncSetAttribute(gemm_bf16<0, 0>, cudaFuncAttributeMaxDynamicSharedMemorySize, SMEM_SZ);
    cudaFuncSetAttribute(gemm_bf16<1, 1>, cudaFuncAttributeMaxDynamicSharedMemorySize, SMEM_SZ);
    cudaFuncSetAttribute(gemm_bf16<2, 0>, cudaFuncAttributeMaxDynamicSharedMemorySize, SMEM_SZ);

    // seq_len==1 => softmax over length-1 axis == 1 => attn == v.
    // a = x @ (Wo@Wv)^T + (Wo@bv + bo): fold both attention GEMMs into one.
    const float* Wv = in_w + (long)2 * DDIM * DDIM;
    const float* bv = in_b + 2 * DDIM;

    // --- prep: conversions (cheap, graph-capturable) ---
    conv_bf16<<<(BSZ * DDIM / 4 + 255) / 256, 256>>>(x, xb, BSZ * DDIM / 4);
    conv_bf16<<<(DDIM * DDIM / 4 + 255) / 256, 256>>>(out_w, wob, DDIM * DDIM / 4);
    transp_bf16<<<dim3(32, 32, 1), 256>>>(Wv, wvt, DDIM, DDIM, 0, 0);
    transp_bf16<<<dim3(32, 32, MMASK), 256>>>(W1, w1b, DDIM, HDIM,
        (long)DDIM * HDIM, (long)HDIM * DDIM);
    transp_bf16<<<dim3(16, 32, MMASK), 256>>>(W2, w2b, HDIM, H2DIM,
        (long)HDIM * H2DIM, (long)H2DIM * HDIM);
    transp_bf16<<<dim3(32, 16, MMASK), 256>>>(W3, w3b, H2DIM, DDIM,
        (long)H2DIM * DDIM, (long)DDIM * H2DIM);
    bc_k<<<DDIM, 256>>>(out_w, bv, out_b, bc);

    // Wc = Wo @ Wv  (bf16 out)
    gemm_bf16<0, 1><<<dim3(8, 8, 1), 128, SMEM_SZ>>>(
        wob, wvt, zeros, wcb, DDIM, DDIM, 0, 0, 0, 0);

    // a = x @ Wc^T + bc  (bf16 out)
    gemm_bf16<0, 1><<<dim3(8, 64, 1), 128, SMEM_SZ>>>(
        xb, wcb, bc, ab, DDIM, DDIM, 0, 0, 0, 0);

    // h1[m] = a @ W1[m] + b1[m]  (f32 out into d_out scratch)
    gemm_bf16<0, 0><<<dim3(8, 64, MMASK), 128, SMEM_SZ>>>(
        ab, w1b, b1, out, HDIM, DDIM,
        0, (long)HDIM * DDIM, (long)HDIM, (long)BSZ * HDIM);

    // LayerNorm + GELU: f32 -> bf16
    ln_gelu_k<<<MMASK * BSZ, 256>>>(out, h1b, ln_g, ln_b);

    // h2[m] = gelu( h1[m] @ W2[m] + b2[m] )  (bf16 out)
    gemm_bf16<1, 1><<<dim3(4, 64, MMASK), 128, SMEM_SZ>>>(
        h1b, w2b, b2, h2b, H2DIM, HDIM,
        (long)BSZ * HDIM, (long)H2DIM * HDIM, (long)H2DIM, (long)BSZ * H2DIM);

    // out[m] = sigmoid( h2[m] @ W3[m] + b3[m] )  (f32 out)
    gemm_bf16<2, 0><<<dim3(8, 64, MMASK), 128, SMEM_SZ>>>(
        h2b, w3b, b3, out, DDIM, H2DIM,
        (long)BSZ * H2DIM, (long)DDIM * H2DIM, (long)DDIM, (long)BSZ * DDIM);
}